// round 1
// baseline (speedup 1.0000x reference)
#include <cuda_runtime.h>

#define B_  2
#define S_  2048
#define E_  1024
#define H_  16
#define D_  64
#define BS_ (B_*S_)

// Scratch (no cudaMalloc allowed): Q,K,V as [B,H,S,D]; ctx as [B,S,H,D] (=concat layout)
__device__ float g_q[(size_t)B_*H_*S_*D_];
__device__ float g_k[(size_t)B_*H_*S_*D_];
__device__ float g_v[(size_t)B_*H_*S_*D_];
__device__ float g_ctx[(size_t)B_*S_*H_*D_];

// ---------------------------------------------------------------------------
// Kernel A: QKV projection. out[b,h,s,d] = sum_e x[b,s,e]*W[h,e,d] + bias[h,d]
// grid: (BS/64, H, 3), block 256 (16x16 threads, 4x4 microtile)
// ---------------------------------------------------------------------------
__global__ __launch_bounds__(256) void qkv_kernel(
    const float* __restrict__ x,
    const float* __restrict__ Wq, const float* __restrict__ bq,
    const float* __restrict__ Wk, const float* __restrict__ bk,
    const float* __restrict__ Wv, const float* __restrict__ bv)
{
    __shared__ float Xs[16][64];  // [kk][row]  (x chunk, transposed)
    __shared__ float Ws[16][64];  // [kk][d]

    const float* W; const float* bias; float* out;
    switch (blockIdx.z) {
        case 0:  W = Wq; bias = bq; out = g_q; break;
        case 1:  W = Wk; bias = bk; out = g_k; break;
        default: W = Wv; bias = bv; out = g_v; break;
    }
    const int h   = blockIdx.y;
    const int m0  = blockIdx.x * 64;
    const int tid = threadIdx.x;
    const int tx  = tid & 15, ty = tid >> 4;

    const float* Wh = W + (size_t)h * E_ * D_;

    float acc[4][4] = {};

    const int lr  = tid >> 2;        // 0..63  (x row)
    const int lc4 = (tid & 3) * 4;   // 0,4,8,12 (x col group within chunk)
    const int wd  = tid & 63;        // d for W load
    const int wk  = tid >> 6;        // 0..3 kk base for W load

    for (int e0 = 0; e0 < E_; e0 += 16) {
        __syncthreads();
        float4 xv = *(const float4*)&x[(size_t)(m0 + lr) * E_ + e0 + lc4];
        Xs[lc4 + 0][lr] = xv.x;
        Xs[lc4 + 1][lr] = xv.y;
        Xs[lc4 + 2][lr] = xv.z;
        Xs[lc4 + 3][lr] = xv.w;
        #pragma unroll
        for (int s = 0; s < 4; s++)
            Ws[wk + 4*s][wd] = Wh[(size_t)(e0 + wk + 4*s) * D_ + wd];
        __syncthreads();

        #pragma unroll
        for (int kk = 0; kk < 16; kk++) {
            float4 a = *(const float4*)&Xs[kk][4*ty];
            float4 b = *(const float4*)&Ws[kk][4*tx];
            float av[4] = {a.x, a.y, a.z, a.w};
            float bw[4] = {b.x, b.y, b.z, b.w};
            #pragma unroll
            for (int i = 0; i < 4; i++)
                #pragma unroll
                for (int j = 0; j < 4; j++)
                    acc[i][j] = fmaf(av[i], bw[j], acc[i][j]);
        }
    }

    #pragma unroll
    for (int i = 0; i < 4; i++) {
        int m  = m0 + 4*ty + i;
        int bb = m >> 11;          // / S_
        int sl = m & (S_ - 1);
        float4 o;
        o.x = acc[i][0] + bias[h*D_ + 4*tx + 0];
        o.y = acc[i][1] + bias[h*D_ + 4*tx + 1];
        o.z = acc[i][2] + bias[h*D_ + 4*tx + 2];
        o.w = acc[i][3] + bias[h*D_ + 4*tx + 3];
        *(float4*)&out[(((size_t)bb*H_ + h)*S_ + sl)*D_ + 4*tx] = o;
    }
}

// ---------------------------------------------------------------------------
// Kernel B: flash attention per (b,h, 64-row q tile). grid (S/64, H, B), 256 thr
// Online softmax with running max/sum; mask applied as reference (-1e9).
// ---------------------------------------------------------------------------
__global__ __launch_bounds__(256) void attn_kernel(const int* __restrict__ mask)
{
    __shared__ float Qs [64][64];  // [d][qrow]
    __shared__ float KPs[64][64];  // phase 1: K as [d][krow]; phase 2: P as [krow][qrow]
    __shared__ float Vs [64][64];  // [krow][d]

    const int q0 = blockIdx.x * 64;
    const int h  = blockIdx.y;
    const int b  = blockIdx.z;

    const size_t base = ((size_t)b*H_ + h) * S_ * D_;
    const float* Q = g_q + base;
    const float* K = g_k + base;
    const float* V = g_v + base;
    const int*   M = mask + (size_t)b * S_ * S_;

    const int tid = threadIdx.x;
    const int tx  = tid & 15, ty = tid >> 4;

    const int lr  = tid >> 2;        // 0..63 (row for transposed loads)
    const int ld0 = (tid & 3) * 16;  // d base (16 d values per thread)
    const int vd4 = (tid & 15) * 4;  // V load col group
    const int vr  = tid >> 4;        // V load row base

    // Q tile, transposed
    #pragma unroll
    for (int u = 0; u < 4; u++) {
        float4 qv = *(const float4*)&Q[(size_t)(q0 + lr) * D_ + ld0 + 4*u];
        Qs[ld0 + 4*u + 0][lr] = qv.x;
        Qs[ld0 + 4*u + 1][lr] = qv.y;
        Qs[ld0 + 4*u + 2][lr] = qv.z;
        Qs[ld0 + 4*u + 3][lr] = qv.w;
    }

    float m_i[4], l_i[4], acc[4][4];
    #pragma unroll
    for (int i = 0; i < 4; i++) {
        m_i[i] = -1e30f; l_i[i] = 0.f;
        #pragma unroll
        for (int j = 0; j < 4; j++) acc[i][j] = 0.f;
    }

    for (int k0 = 0; k0 < S_; k0 += 64) {
        __syncthreads();   // prior-iter KPs/Vs reads done; also fences Qs load on iter 0
        // K tile, transposed
        #pragma unroll
        for (int u = 0; u < 4; u++) {
            float4 kv = *(const float4*)&K[(size_t)(k0 + lr) * D_ + ld0 + 4*u];
            KPs[ld0 + 4*u + 0][lr] = kv.x;
            KPs[ld0 + 4*u + 1][lr] = kv.y;
            KPs[ld0 + 4*u + 2][lr] = kv.z;
            KPs[ld0 + 4*u + 3][lr] = kv.w;
        }
        // V tile, direct
        #pragma unroll
        for (int t = 0; t < 4; t++)
            *(float4*)&Vs[vr + 16*t][vd4] =
                *(const float4*)&V[(size_t)(k0 + vr + 16*t) * D_ + vd4];
        __syncthreads();

        // scores s = Q K^T
        float s[4][4] = {};
        #pragma unroll 16
        for (int d = 0; d < 64; d++) {
            float4 a = *(const float4*)&Qs[d][4*ty];
            float4 c = *(const float4*)&KPs[d][4*tx];
            float av[4] = {a.x, a.y, a.z, a.w};
            float cv[4] = {c.x, c.y, c.z, c.w};
            #pragma unroll
            for (int i = 0; i < 4; i++)
                #pragma unroll
                for (int j = 0; j < 4; j++)
                    s[i][j] = fmaf(av[i], cv[j], s[i][j]);
        }

        // mask + scale + online softmax update
        float p[4][4];
        #pragma unroll
        for (int i = 0; i < 4; i++) {
            int4 mv = *(const int4*)&M[(size_t)(q0 + 4*ty + i) * S_ + k0 + 4*tx];
            float sv[4];
            sv[0] = mv.x ? s[i][0] * 0.125f : -1e9f;
            sv[1] = mv.y ? s[i][1] * 0.125f : -1e9f;
            sv[2] = mv.z ? s[i][2] * 0.125f : -1e9f;
            sv[3] = mv.w ? s[i][3] * 0.125f : -1e9f;
            float mx = fmaxf(fmaxf(sv[0], sv[1]), fmaxf(sv[2], sv[3]));
            #pragma unroll
            for (int off = 1; off < 16; off <<= 1)
                mx = fmaxf(mx, __shfl_xor_sync(0xffffffffu, mx, off));
            float mnew = fmaxf(m_i[i], mx);
            float f    = __expf(m_i[i] - mnew);
            float sum  = 0.f;
            #pragma unroll
            for (int j = 0; j < 4; j++) { p[i][j] = __expf(sv[j] - mnew); sum += p[i][j]; }
            #pragma unroll
            for (int off = 1; off < 16; off <<= 1)
                sum += __shfl_xor_sync(0xffffffffu, sum, off);
            l_i[i] = l_i[i] * f + sum;
            m_i[i] = mnew;
            #pragma unroll
            for (int j = 0; j < 4; j++) acc[i][j] *= f;
        }

        __syncthreads();   // K reads of KPs done
        // store P transposed: KPs[kcol][qrow]
        #pragma unroll
        for (int j = 0; j < 4; j++) {
            float4 w = make_float4(p[0][j], p[1][j], p[2][j], p[3][j]);
            *(float4*)&KPs[4*tx + j][4*ty] = w;
        }
        __syncthreads();

        // acc += P V
        #pragma unroll 16
        for (int k = 0; k < 64; k++) {
            float4 a  = *(const float4*)&KPs[k][4*ty];
            float4 vv = *(const float4*)&Vs[k][4*tx];
            float av[4] = {a.x, a.y, a.z, a.w};
            float vw[4] = {vv.x, vv.y, vv.z, vv.w};
            #pragma unroll
            for (int i = 0; i < 4; i++)
                #pragma unroll
                for (int j = 0; j < 4; j++)
                    acc[i][j] = fmaf(av[i], vw[j], acc[i][j]);
        }
    }

    // normalize and write ctx[b, s, h, d]
    #pragma unroll
    for (int i = 0; i < 4; i++) {
        float inv = 1.0f / l_i[i];
        float4 o = make_float4(acc[i][0]*inv, acc[i][1]*inv, acc[i][2]*inv, acc[i][3]*inv);
        *(float4*)&g_ctx[(((size_t)b*S_ + q0 + 4*ty + i)*H_ + h)*D_ + 4*tx] = o;
    }
}

// ---------------------------------------------------------------------------
// Kernel C: output projection. out[m,n] = sum_k ctx[m,k]*Wo[k,n] + bo[n]
// grid: (BS/64, E/64), block 256
// ---------------------------------------------------------------------------
__global__ __launch_bounds__(256) void oproj_kernel(
    const float* __restrict__ Wo, const float* __restrict__ bo,
    float* __restrict__ out)
{
    __shared__ float Xs[16][64];
    __shared__ float Ws[16][64];

    const int m0  = blockIdx.x * 64;
    const int n0  = blockIdx.y * 64;
    const int tid = threadIdx.x;
    const int tx  = tid & 15, ty = tid >> 4;

    float acc[4][4] = {};

    const int lr  = tid >> 2;
    const int lc4 = (tid & 3) * 4;
    const int wd  = tid & 63;
    const int wk  = tid >> 6;

    const float* ctx = g_ctx;

    for (int e0 = 0; e0 < E_; e0 += 16) {
        __syncthreads();
        float4 xv = *(const float4*)&ctx[(size_t)(m0 + lr) * E_ + e0 + lc4];
        Xs[lc4 + 0][lr] = xv.x;
        Xs[lc4 + 1][lr] = xv.y;
        Xs[lc4 + 2][lr] = xv.z;
        Xs[lc4 + 3][lr] = xv.w;
        #pragma unroll
        for (int s = 0; s < 4; s++)
            Ws[wk + 4*s][wd] = Wo[(size_t)(e0 + wk + 4*s) * E_ + n0 + wd];
        __syncthreads();

        #pragma unroll
        for (int kk = 0; kk < 16; kk++) {
            float4 a = *(const float4*)&Xs[kk][4*ty];
            float4 b = *(const float4*)&Ws[kk][4*tx];
            float av[4] = {a.x, a.y, a.z, a.w};
            float bw[4] = {b.x, b.y, b.z, b.w};
            #pragma unroll
            for (int i = 0; i < 4; i++)
                #pragma unroll
                for (int j = 0; j < 4; j++)
                    acc[i][j] = fmaf(av[i], bw[j], acc[i][j]);
        }
    }

    #pragma unroll
    for (int i = 0; i < 4; i++) {
        int m = m0 + 4*ty + i;
        float4 o;
        o.x = acc[i][0] + bo[n0 + 4*tx + 0];
        o.y = acc[i][1] + bo[n0 + 4*tx + 1];
        o.z = acc[i][2] + bo[n0 + 4*tx + 2];
        o.w = acc[i][3] + bo[n0 + 4*tx + 3];
        *(float4*)&out[(size_t)m * E_ + n0 + 4*tx] = o;
    }
}

// ---------------------------------------------------------------------------
extern "C" void kernel_launch(void* const* d_in, const int* in_sizes, int n_in,
                              void* d_out, int out_size)
{
    const float* x    = (const float*)d_in[0];
    const int*   mask = (const int*)  d_in[1];
    const float* Wq   = (const float*)d_in[2];
    const float* bq   = (const float*)d_in[3];
    const float* Wk   = (const float*)d_in[4];
    const float* bk   = (const float*)d_in[5];
    const float* Wv   = (const float*)d_in[6];
    const float* bv   = (const float*)d_in[7];
    const float* Wo   = (const float*)d_in[8];
    const float* bo   = (const float*)d_in[9];
    float* out = (float*)d_out;

    dim3 gA(BS_/64, H_, 3);
    qkv_kernel<<<gA, 256>>>(x, Wq, bq, Wk, bk, Wv, bv);

    dim3 gB(S_/64, H_, B_);
    attn_kernel<<<gB, 256>>>(mask);

    dim3 gC(BS_/64, E_/64);
    oproj_kernel<<<gC, 256>>>(Wo, bo, out);
}